// round 16
// baseline (speedup 1.0000x reference)
#include <cuda_runtime.h>
#include <cuda_bf16.h>
#include <math.h>
#include <math_constants.h>
#include <stdint.h>

#define BATCH 4096
#define POOL  1024
#define SEL   5
#define PLEN  5
#define DIM   768
#define EPS   1e-8f
#define NCAND 12
#define NROUNDS (NCAND / 2)
#define U32MAX 0xFFFFFFFFu

// ---------------- scratch (device globals; no allocation allowed) ----------
__device__ __nv_bfloat16 g_A[(size_t)BATCH * DIM];  // 6.3 MB
__device__ __nv_bfloat16 g_B[(size_t)POOL  * DIM];  // 1.6 MB (pre-scaled by 1/kn)
__device__ float g_dots[(size_t)BATCH * POOL];      // 16.8 MB (already d/kn)
__device__ float g_kn[POOL];
__device__ float g_qn[BATCH];

// ---------------- PTX helpers (sm_80-compatible only: no tcgen05) ----------
__device__ __forceinline__ uint32_t smem_u32(const void* p) {
    uint32_t a;
    asm("{ .reg .u64 t; cvta.to.shared.u64 t, %1; cvt.u32.u64 %0, t; }" : "=r"(a) : "l"(p));
    return a;
}
__device__ __forceinline__ void cp_async16(uint32_t saddr, const void* gptr) {
    asm volatile("cp.async.cg.shared.global [%0], [%1], 16;"
                 :: "r"(saddr), "l"(gptr) : "memory");
}
__device__ __forceinline__ void cp_commit() {
    asm volatile("cp.async.commit_group;" ::: "memory");
}
template <int N>
__device__ __forceinline__ void cp_wait() {
    asm volatile("cp.async.wait_group %0;" :: "n"(N) : "memory");
}
__device__ __forceinline__ void ldmatrix_x4(uint32_t* r, uint32_t addr) {
    asm volatile("ldmatrix.sync.aligned.m8n8.x4.shared.b16 {%0,%1,%2,%3}, [%4];"
                 : "=r"(r[0]), "=r"(r[1]), "=r"(r[2]), "=r"(r[3]) : "r"(addr));
}
__device__ __forceinline__ void ldmatrix_x2(uint32_t* r, uint32_t addr) {
    asm volatile("ldmatrix.sync.aligned.m8n8.x2.shared.b16 {%0,%1}, [%2];"
                 : "=r"(r[0]), "=r"(r[1]) : "r"(addr));
}
__device__ __forceinline__ void mma_bf16(float* c, const uint32_t* a, const uint32_t* b) {
    asm volatile(
        "mma.sync.aligned.m16n8k16.row.col.f32.bf16.bf16.f32 "
        "{%0,%1,%2,%3}, {%4,%5,%6,%7}, {%8,%9}, {%0,%1,%2,%3};"
        : "+f"(c[0]), "+f"(c[1]), "+f"(c[2]), "+f"(c[3])
        : "r"(a[0]), "r"(a[1]), "r"(a[2]), "r"(a[3]), "r"(b[0]), "r"(b[1]));
}

// orderable-uint encoding of float (monotonic: a<b  <=>  enc(a)<enc(b))
__device__ __forceinline__ uint32_t ford(float f) {
    uint32_t u = __float_as_uint(f);
    return u ^ (((int32_t)u >> 31) | 0x80000000u);
}

// merge two (min, 2nd-min) u32 pairs
__device__ __forceinline__ void pmerge(uint32_t& m1, uint32_t& m2,
                                       uint32_t o1, uint32_t o2) {
    uint32_t n1 = min(m1, o1);
    uint32_t n2 = min(max(m1, o1), min(m2, o2));
    m1 = n1; m2 = n2;
}

// ============================================================
// Fused conversion + norms. One block (384 threads) per row.
//   blocks [0, BATCH)          : Q row -> bf16 g_A + g_qn
//   blocks [BATCH, BATCH+POOL) : K row -> kn, bf16(k/kn) -> g_B, g_kn
// ============================================================
__global__ __launch_bounds__(384) void conv_kernel(const float* __restrict__ q,
                                                   const float* __restrict__ kp) {
    const int tid = threadIdx.x;
    const int wid = tid >> 5, lid = tid & 31;
    __shared__ float ws[12];

    if (blockIdx.x < BATCH) {
        const int row = blockIdx.x;
        float2 f = ((const float2*)q)[(size_t)row * (DIM / 2) + tid];
        ((__nv_bfloat162*)g_A)[(size_t)row * (DIM / 2) + tid] =
            make_bfloat162(__float2bfloat16(f.x), __float2bfloat16(f.y));
        float s = f.x * f.x + f.y * f.y;
        #pragma unroll
        for (int o = 16; o > 0; o >>= 1) s += __shfl_down_sync(0xFFFFFFFFu, s, o);
        if (lid == 0) ws[wid] = s;
        __syncthreads();
        if (tid == 0) {
            float t = 0.f;
            #pragma unroll
            for (int w = 0; w < 12; w++) t += ws[w];
            g_qn[row] = sqrtf(t);
        }
    } else {
        const int row = blockIdx.x - BATCH;
        float2 f = ((const float2*)kp)[(size_t)row * (DIM / 2) + tid];
        float s = f.x * f.x + f.y * f.y;
        #pragma unroll
        for (int o = 16; o > 0; o >>= 1) s += __shfl_down_sync(0xFFFFFFFFu, s, o);
        if (lid == 0) ws[wid] = s;
        __syncthreads();
        float t = 0.f;
        #pragma unroll
        for (int w = 0; w < 12; w++) t += ws[w];
        const float kn = sqrtf(t);
        if (tid == 0) g_kn[row] = kn;
        const float rkn = 1.0f / kn;
        ((__nv_bfloat162*)g_B)[(size_t)row * (DIM / 2) + tid] =
            make_bfloat162(__float2bfloat16(f.x * rkn), __float2bfloat16(f.y * rkn));
    }
}

// ============================================================
// HMMA bf16 GEMM: dots[4096,1024] = A[4096,768] @ Bhat[1024,768]^T
// ============================================================
#define BM 128
#define BN 128
#define BK 64
#define STAGES 3
#define NT (DIM / BK)                  // 12
#define A_STAGE_BYTES (BM * BK * 2)    // 16384
#define STAGE_BYTES   (2 * A_STAGE_BYTES)
#define GEMM_SMEM     (STAGES * STAGE_BYTES)   // 98304

__device__ __forceinline__ uint32_t sw_off(int row, int chunk) {
    return (uint32_t)(row * 128 + ((chunk ^ (row & 7)) * 16));
}

__global__ __launch_bounds__(256, 2) void gemm_hmma_kernel() {
    extern __shared__ char smem[];
    const uint32_t sb = smem_u32(smem);
    const int tid = threadIdx.x;
    const int wid = tid >> 5, lid = tid & 31;
    const int bm = blockIdx.y * BM;
    const int bn = blockIdx.x * BN;
    const int wm = (wid >> 2) * 64;
    const int wn = (wid & 3) * 32;

    float acc[4][4][4];
    #pragma unroll
    for (int i = 0; i < 4; i++)
        #pragma unroll
        for (int j = 0; j < 4; j++)
            #pragma unroll
            for (int c = 0; c < 4; c++) acc[i][j][c] = 0.f;

    uint32_t soff[4];
    const __nv_bfloat16 *pa[4], *pb[4];
    {
        const __nv_bfloat16* gA = g_A + (size_t)bm * DIM;
        const __nv_bfloat16* gB = g_B + (size_t)bn * DIM;
        #pragma unroll
        for (int j = 0; j < 4; j++) {
            int idx = j * 256 + tid;
            int row = idx >> 3, ch = idx & 7;
            soff[j] = sw_off(row, ch);
            pa[j] = gA + (size_t)row * DIM + ch * 8;
            pb[j] = gB + (size_t)row * DIM + ch * 8;
        }
    }

    #define LOAD_STAGE(s, t)                                                   \
        {                                                                      \
            uint32_t ab = sb + (s) * STAGE_BYTES;                              \
            uint32_t bb = ab + A_STAGE_BYTES;                                  \
            _Pragma("unroll")                                                  \
            for (int j = 0; j < 4; j++) {                                      \
                cp_async16(ab + soff[j], pa[j] + (t) * BK);                    \
                cp_async16(bb + soff[j], pb[j] + (t) * BK);                    \
            }                                                                  \
        }

    LOAD_STAGE(0, 0); cp_commit();
    LOAD_STAGE(1, 1); cp_commit();

    const int ar0 = wm + (lid & 15);
    const int ach = (lid >> 4);
    const int br0 = wn + (lid & 7);
    const int bch = ((lid >> 3) & 1);

    for (int t = 0; t < NT; t++) {
        cp_wait<STAGES - 2>();
        __syncthreads();

        int tn = t + STAGES - 1;
        if (tn < NT) LOAD_STAGE(tn % STAGES, tn);
        cp_commit();

        const uint32_t ab = sb + (t % STAGES) * STAGE_BYTES;
        const uint32_t bb = ab + A_STAGE_BYTES;

        #pragma unroll
        for (int k16 = 0; k16 < BK / 16; k16++) {
            uint32_t afr[4][4], bfr[4][2];
            #pragma unroll
            for (int mi = 0; mi < 4; mi++)
                ldmatrix_x4(afr[mi], ab + sw_off(ar0 + mi * 16, k16 * 2 + ach));
            #pragma unroll
            for (int ni = 0; ni < 4; ni++)
                ldmatrix_x2(bfr[ni], bb + sw_off(br0 + ni * 8, k16 * 2 + bch));
            #pragma unroll
            for (int mi = 0; mi < 4; mi++)
                #pragma unroll
                for (int ni = 0; ni < 4; ni++)
                    mma_bf16(acc[mi][ni], afr[mi], bfr[ni]);
        }
        __syncthreads();
    }

    const int rbase = bm + wm + (lid >> 2);
    const int cbase = bn + wn + (lid & 3) * 2;
    #pragma unroll
    for (int mi = 0; mi < 4; mi++) {
        #pragma unroll
        for (int ni = 0; ni < 4; ni++) {
            float* p = g_dots + (size_t)(rbase + mi * 16) * POOL + cbase + ni * 8;
            *(float2*)p              = make_float2(acc[mi][ni][0], acc[mi][ni][1]);
            *(float2*)(p + 8 * POOL) = make_float2(acc[mi][ni][2], acc[mi][ni][3]);
        }
    }
}

// ============================================================
// FUSED topk + gather. dots pre-scaled (d/kn): ranking key is
// (ford(-d) & ~1023) | pool_index, loaded via float4 (p = tid*4+j).
// 6 extraction rounds x 2 candidates, 1 barrier each; exact fp32
// rescore of 12; exact top-5; MLP-pipelined gather.
// ============================================================
__global__ __launch_bounds__(256)
void topk_gather_kernel(const float* __restrict__ query, const float* __restrict__ key,
                        const float* __restrict__ prompts,
                        float* __restrict__ sim_out, float* __restrict__ sel_out) {
    const int b = blockIdx.x;
    const int tid = threadIdx.x;
    const int wid = tid >> 5, lid = tid & 31;

    __shared__ uint32_t s_wp[2][16];   // double-buffered: 8 warps x (m1, m2)
    __shared__ int   s_top[NCAND];
    __shared__ float s_cval[NCAND];
    __shared__ int   s_sel[SEL];

    // --- 32-bit ranking keys via one float4 load (p = tid*4 + j) ---
    uint32_t v32[4];
    {
        float4 d4 = ((const float4*)(g_dots + (size_t)b * POOL))[tid];
        v32[0] = (ford(-d4.x) & 0xFFFFFC00u) | (uint32_t)(tid * 4 + 0);
        v32[1] = (ford(-d4.y) & 0xFFFFFC00u) | (uint32_t)(tid * 4 + 1);
        v32[2] = (ford(-d4.z) & 0xFFFFFC00u) | (uint32_t)(tid * 4 + 2);
        v32[3] = (ford(-d4.w) & 0xFFFFFC00u) | (uint32_t)(tid * 4 + 3);
    }

    // --- 6 rounds x 2 candidates, 1 barrier each ---
    #pragma unroll
    for (int r = 0; r < NROUNDS; r++) {
        uint32_t a1 = min(v32[0], v32[1]), a2 = max(v32[0], v32[1]);
        uint32_t b1 = min(v32[2], v32[3]), b2 = max(v32[2], v32[3]);
        uint32_t m1 = min(a1, b1);
        uint32_t m2 = min(max(a1, b1), min(a2, b2));
        #pragma unroll
        for (int o = 16; o > 0; o >>= 1) {
            uint32_t o1 = __shfl_xor_sync(0xFFFFFFFFu, m1, o);
            uint32_t o2 = __shfl_xor_sync(0xFFFFFFFFu, m2, o);
            pmerge(m1, m2, o1, o2);
        }
        const int buf = r & 1;
        if (lid == 0) { s_wp[buf][wid * 2] = m1; s_wp[buf][wid * 2 + 1] = m2; }
        __syncthreads();
        // ALL lanes load (lid & 15) so the butterfly covers every lane
        uint32_t x1 = s_wp[buf][lid & 15];
        uint32_t x2 = U32MAX;
        #pragma unroll
        for (int o = 8; o > 0; o >>= 1) {
            uint32_t o1 = __shfl_xor_sync(0xFFFFFFFFu, x1, o);
            uint32_t o2 = __shfl_xor_sync(0xFFFFFFFFu, x2, o);
            pmerge(x1, x2, o1, o2);
        }
        if (tid == 0) {
            s_top[r * 2]     = (int)(x1 & 1023u);
            s_top[r * 2 + 1] = (int)(x2 & 1023u);
        }
        #pragma unroll
        for (int j = 0; j < 4; j++)
            if (v32[j] == x1 || v32[j] == x2) v32[j] = U32MAX;
    }
    __syncthreads();       // s_top visible to all

    // --- exact fp32 rescore: warp w -> cand w; warps 0-3 also cand w+8 ---
    const float* qrow = query + (size_t)b * DIM;
    {
        const int c1 = s_top[wid];
        const int c2 = (wid < 4) ? s_top[wid + 8] : 0;
        const float* k1 = key + (size_t)c1 * DIM;
        const float* k2 = key + (size_t)c2 * DIM;
        float d1 = 0.f, d2 = 0.f;
        if (wid < 4) {
            #pragma unroll
            for (int j = 0; j < DIM / 32; j++) {
                int i = lid + j * 32;
                float qv = qrow[i];
                d1 = fmaf(qv, k1[i], d1);
                d2 = fmaf(qv, k2[i], d2);
            }
        } else {
            #pragma unroll
            for (int j = 0; j < DIM / 32; j++) {
                int i = lid + j * 32;
                d1 = fmaf(qrow[i], k1[i], d1);
            }
        }
        #pragma unroll
        for (int o = 16; o > 0; o >>= 1) {
            d1 += __shfl_down_sync(0xFFFFFFFFu, d1, o);
            d2 += __shfl_down_sync(0xFFFFFFFFu, d2, o);
        }
        if (lid == 0) {
            const float qn = g_qn[b];
            s_cval[wid] = 1.0f - d1 / fmaxf(qn * g_kn[c1], EPS);
            if (wid < 4)
                s_cval[wid + 8] = 1.0f - d2 / fmaxf(qn * g_kn[c2], EPS);
        }
    }
    __syncthreads();

    // --- final top-5 among 12 rescored candidates (value, then index) ---
    if (tid == 0) {
        float cv[NCAND]; int ci[NCAND];
        #pragma unroll
        for (int j = 0; j < NCAND; j++) { cv[j] = s_cval[j]; ci[j] = s_top[j]; }
        #pragma unroll
        for (int a = 1; a < NCAND; a++) {
            float v = cv[a]; int x = ci[a];
            int p = a - 1;
            while (p >= 0 && (cv[p] > v || (cv[p] == v && ci[p] > x))) {
                cv[p + 1] = cv[p]; ci[p + 1] = ci[p]; p--;
            }
            cv[p + 1] = v; ci[p + 1] = x;
        }
        #pragma unroll
        for (int j = 0; j < SEL; j++) {
            sim_out[b * SEL + j] = cv[j];
            s_sel[j] = ci[j];
        }
    }
    __syncthreads();

    // --- gather: 5 prompts x 960 float4; 4-deep load/store pipeline ---
    const bool pr = (tid < 192);       // 960 = 3*256 + 192
    #pragma unroll
    for (int sidx = 0; sidx < SEL; sidx++) {
        const int p = s_sel[sidx];
        const float4* src = (const float4*)(prompts + (size_t)p * PLEN * DIM);
        float4* dst = (float4*)(sel_out + ((size_t)b * SEL + sidx) * PLEN * DIM);
        float4 v0 = __ldg(src + tid);
        float4 v1 = __ldg(src + tid + 256);
        float4 v2 = __ldg(src + tid + 512);
        float4 v3;
        if (pr) v3 = __ldg(src + tid + 768);
        __stcs(dst + tid,       v0);
        __stcs(dst + tid + 256, v1);
        __stcs(dst + tid + 512, v2);
        if (pr) __stcs(dst + tid + 768, v3);
    }
}

// ============================================================
extern "C" void kernel_launch(void* const* d_in, const int* in_sizes, int n_in,
                              void* d_out, int out_size) {
    const float* query   = (const float*)d_in[0];  // [4096, 768]
    const float* key     = (const float*)d_in[1];  // [1024, 768]
    const float* prompts = (const float*)d_in[2];  // [1024, 5, 768]

    float* sim_out = (float*)d_out;                        // [4096, 5]
    float* sel_out = (float*)d_out + (size_t)BATCH * SEL;  // [4096, 5, 5, 768]

    cudaFuncSetAttribute(gemm_hmma_kernel,
                         cudaFuncAttributeMaxDynamicSharedMemorySize, GEMM_SMEM);

    conv_kernel<<<BATCH + POOL, 384>>>(query, key);

    dim3 ggrid(POOL / BN, BATCH / BM);   // (8, 32)
    gemm_hmma_kernel<<<ggrid, 256, GEMM_SMEM>>>();

    topk_gather_kernel<<<BATCH, 256>>>(query, key, prompts, sim_out, sel_out);
}

// round 17
// speedup vs baseline: 1.0624x; 1.0624x over previous
#include <cuda_runtime.h>
#include <cuda_bf16.h>
#include <math.h>
#include <math_constants.h>
#include <stdint.h>

#define BATCH 4096
#define POOL  1024
#define SEL   5
#define PLEN  5
#define DIM   768
#define EPS   1e-8f
#define NCAND 12
#define NROUNDS (NCAND / 2)
#define U32MAX 0xFFFFFFFFu

// ---------------- scratch (device globals; no allocation allowed) ----------
__device__ __nv_bfloat16 g_A[(size_t)BATCH * DIM];  // 6.3 MB
__device__ __nv_bfloat16 g_B[(size_t)POOL  * DIM];  // 1.6 MB (pre-scaled by 1/kn)
__device__ float g_dots[(size_t)BATCH * POOL];      // 16.8 MB (already d/kn)
__device__ float g_kn[POOL];
__device__ float g_qn[BATCH];

// ---------------- PTX helpers (sm_80-compatible only: no tcgen05) ----------
__device__ __forceinline__ uint32_t smem_u32(const void* p) {
    uint32_t a;
    asm("{ .reg .u64 t; cvta.to.shared.u64 t, %1; cvt.u32.u64 %0, t; }" : "=r"(a) : "l"(p));
    return a;
}
__device__ __forceinline__ void cp_async16(uint32_t saddr, const void* gptr) {
    asm volatile("cp.async.cg.shared.global [%0], [%1], 16;"
                 :: "r"(saddr), "l"(gptr) : "memory");
}
__device__ __forceinline__ void cp_commit() {
    asm volatile("cp.async.commit_group;" ::: "memory");
}
template <int N>
__device__ __forceinline__ void cp_wait() {
    asm volatile("cp.async.wait_group %0;" :: "n"(N) : "memory");
}
__device__ __forceinline__ void ldmatrix_x4(uint32_t* r, uint32_t addr) {
    asm volatile("ldmatrix.sync.aligned.m8n8.x4.shared.b16 {%0,%1,%2,%3}, [%4];"
                 : "=r"(r[0]), "=r"(r[1]), "=r"(r[2]), "=r"(r[3]) : "r"(addr));
}
__device__ __forceinline__ void ldmatrix_x2(uint32_t* r, uint32_t addr) {
    asm volatile("ldmatrix.sync.aligned.m8n8.x2.shared.b16 {%0,%1}, [%2];"
                 : "=r"(r[0]), "=r"(r[1]) : "r"(addr));
}
__device__ __forceinline__ void mma_bf16(float* c, const uint32_t* a, const uint32_t* b) {
    asm volatile(
        "mma.sync.aligned.m16n8k16.row.col.f32.bf16.bf16.f32 "
        "{%0,%1,%2,%3}, {%4,%5,%6,%7}, {%8,%9}, {%0,%1,%2,%3};"
        : "+f"(c[0]), "+f"(c[1]), "+f"(c[2]), "+f"(c[3])
        : "r"(a[0]), "r"(a[1]), "r"(a[2]), "r"(a[3]), "r"(b[0]), "r"(b[1]));
}

// orderable-uint encoding of float (monotonic: a<b  <=>  enc(a)<enc(b))
__device__ __forceinline__ uint32_t ford(float f) {
    uint32_t u = __float_as_uint(f);
    return u ^ (((int32_t)u >> 31) | 0x80000000u);
}

// merge two (min, 2nd-min) u32 pairs
__device__ __forceinline__ void pmerge(uint32_t& m1, uint32_t& m2,
                                       uint32_t o1, uint32_t o2) {
    uint32_t n1 = min(m1, o1);
    uint32_t n2 = min(max(m1, o1), min(m2, o2));
    m1 = n1; m2 = n2;
}

__device__ __forceinline__ uint32_t bf2_pack(float a, float b) {
    __nv_bfloat162 h = make_bfloat162(__float2bfloat16(a), __float2bfloat16(b));
    return *reinterpret_cast<uint32_t*>(&h);
}

// ============================================================
// Warp-per-row conversion + norms. 8 warps/block, no block barriers.
//   warps [0, BATCH)          : Q row -> bf16 g_A + g_qn
//   warps [BATCH, BATCH+POOL) : K row -> kn, bf16(k/kn) -> g_B, g_kn
// Each lane: 6 x float4 (24 floats), warp shuffle reduce.
// ============================================================
#define CONV_BLOCKS ((BATCH + POOL) / 8)    // 640
__global__ __launch_bounds__(256) void conv_kernel(const float* __restrict__ q,
                                                   const float* __restrict__ kp) {
    const int gw = blockIdx.x * 8 + (threadIdx.x >> 5);
    const int lid = threadIdx.x & 31;

    if (gw < BATCH) {
        const int row = gw;
        const float4* src = (const float4*)(q + (size_t)row * DIM);
        uint2* dst = (uint2*)(g_A + (size_t)row * DIM);
        float s = 0.f;
        #pragma unroll
        for (int j = 0; j < 6; j++) {
            float4 f = src[lid + j * 32];
            s = fmaf(f.x, f.x, fmaf(f.y, f.y, fmaf(f.z, f.z, fmaf(f.w, f.w, s))));
            dst[lid + j * 32] = make_uint2(bf2_pack(f.x, f.y), bf2_pack(f.z, f.w));
        }
        #pragma unroll
        for (int o = 16; o > 0; o >>= 1) s += __shfl_down_sync(0xFFFFFFFFu, s, o);
        if (lid == 0) g_qn[row] = sqrtf(s);
    } else {
        const int row = gw - BATCH;
        const float4* src = (const float4*)(kp + (size_t)row * DIM);
        uint2* dst = (uint2*)(g_B + (size_t)row * DIM);
        float4 f[6];
        float s = 0.f;
        #pragma unroll
        for (int j = 0; j < 6; j++) {
            f[j] = src[lid + j * 32];
            s = fmaf(f[j].x, f[j].x, fmaf(f[j].y, f[j].y,
                fmaf(f[j].z, f[j].z, fmaf(f[j].w, f[j].w, s))));
        }
        #pragma unroll
        for (int o = 16; o > 0; o >>= 1) s += __shfl_xor_sync(0xFFFFFFFFu, s, o);
        const float kn = sqrtf(s);
        if (lid == 0) g_kn[row] = kn;
        const float rkn = 1.0f / kn;
        #pragma unroll
        for (int j = 0; j < 6; j++) {
            dst[lid + j * 32] = make_uint2(bf2_pack(f[j].x * rkn, f[j].y * rkn),
                                           bf2_pack(f[j].z * rkn, f[j].w * rkn));
        }
    }
}

// ============================================================
// HMMA bf16 GEMM: dots[4096,1024] = A[4096,768] @ Bhat[1024,768]^T
// ============================================================
#define BM 128
#define BN 128
#define BK 64
#define STAGES 3
#define NT (DIM / BK)                  // 12
#define A_STAGE_BYTES (BM * BK * 2)    // 16384
#define STAGE_BYTES   (2 * A_STAGE_BYTES)
#define GEMM_SMEM     (STAGES * STAGE_BYTES)   // 98304

__device__ __forceinline__ uint32_t sw_off(int row, int chunk) {
    return (uint32_t)(row * 128 + ((chunk ^ (row & 7)) * 16));
}

__global__ __launch_bounds__(256, 2) void gemm_hmma_kernel() {
    extern __shared__ char smem[];
    const uint32_t sb = smem_u32(smem);
    const int tid = threadIdx.x;
    const int wid = tid >> 5, lid = tid & 31;
    const int bm = blockIdx.y * BM;
    const int bn = blockIdx.x * BN;
    const int wm = (wid >> 2) * 64;
    const int wn = (wid & 3) * 32;

    float acc[4][4][4];
    #pragma unroll
    for (int i = 0; i < 4; i++)
        #pragma unroll
        for (int j = 0; j < 4; j++)
            #pragma unroll
            for (int c = 0; c < 4; c++) acc[i][j][c] = 0.f;

    uint32_t soff[4];
    const __nv_bfloat16 *pa[4], *pb[4];
    {
        const __nv_bfloat16* gA = g_A + (size_t)bm * DIM;
        const __nv_bfloat16* gB = g_B + (size_t)bn * DIM;
        #pragma unroll
        for (int j = 0; j < 4; j++) {
            int idx = j * 256 + tid;
            int row = idx >> 3, ch = idx & 7;
            soff[j] = sw_off(row, ch);
            pa[j] = gA + (size_t)row * DIM + ch * 8;
            pb[j] = gB + (size_t)row * DIM + ch * 8;
        }
    }

    #define LOAD_STAGE(s, t)                                                   \
        {                                                                      \
            uint32_t ab = sb + (s) * STAGE_BYTES;                              \
            uint32_t bb = ab + A_STAGE_BYTES;                                  \
            _Pragma("unroll")                                                  \
            for (int j = 0; j < 4; j++) {                                      \
                cp_async16(ab + soff[j], pa[j] + (t) * BK);                    \
                cp_async16(bb + soff[j], pb[j] + (t) * BK);                    \
            }                                                                  \
        }

    LOAD_STAGE(0, 0); cp_commit();
    LOAD_STAGE(1, 1); cp_commit();

    const int ar0 = wm + (lid & 15);
    const int ach = (lid >> 4);
    const int br0 = wn + (lid & 7);
    const int bch = ((lid >> 3) & 1);

    for (int t = 0; t < NT; t++) {
        cp_wait<STAGES - 2>();
        __syncthreads();

        int tn = t + STAGES - 1;
        if (tn < NT) LOAD_STAGE(tn % STAGES, tn);
        cp_commit();

        const uint32_t ab = sb + (t % STAGES) * STAGE_BYTES;
        const uint32_t bb = ab + A_STAGE_BYTES;

        #pragma unroll
        for (int k16 = 0; k16 < BK / 16; k16++) {
            uint32_t afr[4][4], bfr[4][2];
            #pragma unroll
            for (int mi = 0; mi < 4; mi++)
                ldmatrix_x4(afr[mi], ab + sw_off(ar0 + mi * 16, k16 * 2 + ach));
            #pragma unroll
            for (int ni = 0; ni < 4; ni++)
                ldmatrix_x2(bfr[ni], bb + sw_off(br0 + ni * 8, k16 * 2 + bch));
            #pragma unroll
            for (int mi = 0; mi < 4; mi++)
                #pragma unroll
                for (int ni = 0; ni < 4; ni++)
                    mma_bf16(acc[mi][ni], afr[mi], bfr[ni]);
        }
        __syncthreads();
    }

    const int rbase = bm + wm + (lid >> 2);
    const int cbase = bn + wn + (lid & 3) * 2;
    #pragma unroll
    for (int mi = 0; mi < 4; mi++) {
        #pragma unroll
        for (int ni = 0; ni < 4; ni++) {
            float* p = g_dots + (size_t)(rbase + mi * 16) * POOL + cbase + ni * 8;
            *(float2*)p              = make_float2(acc[mi][ni][0], acc[mi][ni][1]);
            *(float2*)(p + 8 * POOL) = make_float2(acc[mi][ni][2], acc[mi][ni][3]);
        }
    }
}

// ============================================================
// FUSED topk + gather. dots pre-scaled (d/kn): ranking key is
// (ford(-d) & ~1023) | pool_index, loaded via float4 (p = tid*4+j).
// 6 extraction rounds x 2 candidates, 1 barrier each; exact fp32
// rescore of 12; exact top-5; MLP-pipelined gather.
// ============================================================
__global__ __launch_bounds__(256)
void topk_gather_kernel(const float* __restrict__ query, const float* __restrict__ key,
                        const float* __restrict__ prompts,
                        float* __restrict__ sim_out, float* __restrict__ sel_out) {
    const int b = blockIdx.x;
    const int tid = threadIdx.x;
    const int wid = tid >> 5, lid = tid & 31;

    __shared__ uint32_t s_wp[2][16];   // double-buffered: 8 warps x (m1, m2)
    __shared__ int   s_top[NCAND];
    __shared__ float s_cval[NCAND];
    __shared__ int   s_sel[SEL];

    // --- 32-bit ranking keys via one float4 load (p = tid*4 + j) ---
    uint32_t v32[4];
    {
        float4 d4 = ((const float4*)(g_dots + (size_t)b * POOL))[tid];
        v32[0] = (ford(-d4.x) & 0xFFFFFC00u) | (uint32_t)(tid * 4 + 0);
        v32[1] = (ford(-d4.y) & 0xFFFFFC00u) | (uint32_t)(tid * 4 + 1);
        v32[2] = (ford(-d4.z) & 0xFFFFFC00u) | (uint32_t)(tid * 4 + 2);
        v32[3] = (ford(-d4.w) & 0xFFFFFC00u) | (uint32_t)(tid * 4 + 3);
    }

    // --- 6 rounds x 2 candidates, 1 barrier each ---
    #pragma unroll
    for (int r = 0; r < NROUNDS; r++) {
        uint32_t a1 = min(v32[0], v32[1]), a2 = max(v32[0], v32[1]);
        uint32_t b1 = min(v32[2], v32[3]), b2 = max(v32[2], v32[3]);
        uint32_t m1 = min(a1, b1);
        uint32_t m2 = min(max(a1, b1), min(a2, b2));
        #pragma unroll
        for (int o = 16; o > 0; o >>= 1) {
            uint32_t o1 = __shfl_xor_sync(0xFFFFFFFFu, m1, o);
            uint32_t o2 = __shfl_xor_sync(0xFFFFFFFFu, m2, o);
            pmerge(m1, m2, o1, o2);
        }
        const int buf = r & 1;
        if (lid == 0) { s_wp[buf][wid * 2] = m1; s_wp[buf][wid * 2 + 1] = m2; }
        __syncthreads();
        // ALL lanes load (lid & 15) so the butterfly covers every lane
        uint32_t x1 = s_wp[buf][lid & 15];
        uint32_t x2 = U32MAX;
        #pragma unroll
        for (int o = 8; o > 0; o >>= 1) {
            uint32_t o1 = __shfl_xor_sync(0xFFFFFFFFu, x1, o);
            uint32_t o2 = __shfl_xor_sync(0xFFFFFFFFu, x2, o);
            pmerge(x1, x2, o1, o2);
        }
        if (tid == 0) {
            s_top[r * 2]     = (int)(x1 & 1023u);
            s_top[r * 2 + 1] = (int)(x2 & 1023u);
        }
        #pragma unroll
        for (int j = 0; j < 4; j++)
            if (v32[j] == x1 || v32[j] == x2) v32[j] = U32MAX;
    }
    __syncthreads();       // s_top visible to all

    // --- exact fp32 rescore: warp w -> cand w; warps 0-3 also cand w+8 ---
    const float* qrow = query + (size_t)b * DIM;
    {
        const int c1 = s_top[wid];
        const int c2 = (wid < 4) ? s_top[wid + 8] : 0;
        const float* k1 = key + (size_t)c1 * DIM;
        const float* k2 = key + (size_t)c2 * DIM;
        float d1 = 0.f, d2 = 0.f;
        if (wid < 4) {
            #pragma unroll
            for (int j = 0; j < DIM / 32; j++) {
                int i = lid + j * 32;
                float qv = qrow[i];
                d1 = fmaf(qv, k1[i], d1);
                d2 = fmaf(qv, k2[i], d2);
            }
        } else {
            #pragma unroll
            for (int j = 0; j < DIM / 32; j++) {
                int i = lid + j * 32;
                d1 = fmaf(qrow[i], k1[i], d1);
            }
        }
        #pragma unroll
        for (int o = 16; o > 0; o >>= 1) {
            d1 += __shfl_down_sync(0xFFFFFFFFu, d1, o);
            d2 += __shfl_down_sync(0xFFFFFFFFu, d2, o);
        }
        if (lid == 0) {
            const float qn = g_qn[b];
            s_cval[wid] = 1.0f - d1 / fmaxf(qn * g_kn[c1], EPS);
            if (wid < 4)
                s_cval[wid + 8] = 1.0f - d2 / fmaxf(qn * g_kn[c2], EPS);
        }
    }
    __syncthreads();

    // --- final top-5 among 12 rescored candidates (value, then index) ---
    if (tid == 0) {
        float cv[NCAND]; int ci[NCAND];
        #pragma unroll
        for (int j = 0; j < NCAND; j++) { cv[j] = s_cval[j]; ci[j] = s_top[j]; }
        #pragma unroll
        for (int a = 1; a < NCAND; a++) {
            float v = cv[a]; int x = ci[a];
            int p = a - 1;
            while (p >= 0 && (cv[p] > v || (cv[p] == v && ci[p] > x))) {
                cv[p + 1] = cv[p]; ci[p + 1] = ci[p]; p--;
            }
            cv[p + 1] = v; ci[p + 1] = x;
        }
        #pragma unroll
        for (int j = 0; j < SEL; j++) {
            sim_out[b * SEL + j] = cv[j];
            s_sel[j] = ci[j];
        }
    }
    __syncthreads();

    // --- gather: 5 prompts x 960 float4; 4-deep load/store pipeline ---
    const bool pr = (tid < 192);       // 960 = 3*256 + 192
    #pragma unroll
    for (int sidx = 0; sidx < SEL; sidx++) {
        const int p = s_sel[sidx];
        const float4* src = (const float4*)(prompts + (size_t)p * PLEN * DIM);
        float4* dst = (float4*)(sel_out + ((size_t)b * SEL + sidx) * PLEN * DIM);
        float4 v0 = __ldg(src + tid);
        float4 v1 = __ldg(src + tid + 256);
        float4 v2 = __ldg(src + tid + 512);
        float4 v3;
        if (pr) v3 = __ldg(src + tid + 768);
        __stcs(dst + tid,       v0);
        __stcs(dst + tid + 256, v1);
        __stcs(dst + tid + 512, v2);
        if (pr) __stcs(dst + tid + 768, v3);
    }
}

// ============================================================
extern "C" void kernel_launch(void* const* d_in, const int* in_sizes, int n_in,
                              void* d_out, int out_size) {
    const float* query   = (const float*)d_in[0];  // [4096, 768]
    const float* key     = (const float*)d_in[1];  // [1024, 768]
    const float* prompts = (const float*)d_in[2];  // [1024, 5, 768]

    float* sim_out = (float*)d_out;                        // [4096, 5]
    float* sel_out = (float*)d_out + (size_t)BATCH * SEL;  // [4096, 5, 5, 768]

    cudaFuncSetAttribute(gemm_hmma_kernel,
                         cudaFuncAttributeMaxDynamicSharedMemorySize, GEMM_SMEM);

    conv_kernel<<<CONV_BLOCKS, 256>>>(query, key);

    dim3 ggrid(POOL / BN, BATCH / BM);   // (8, 32)
    gemm_hmma_kernel<<<ggrid, 256, GEMM_SMEM>>>();

    topk_gather_kernel<<<BATCH, 256>>>(query, key, prompts, sim_out, sel_out);
}